// round 15
// baseline (speedup 1.0000x reference)
#include <cuda_runtime.h>
#include <cstdint>
#include <math.h>

#define BB 4
#define NN 512
#define DD 4
#define HH 256

// ---------------- device scratch (allocation-free) ----------------
__device__ float g_U[BB*NN*HH];    // x @ W_e1[:D]
__device__ float g_V[BB*NN*HH];    // x @ W_e1[D:] + b_e1
__device__ float g_agg[BB*NN*HH];  // adjacency-reduced edge features

// ---------------- helpers ----------------
__device__ __forceinline__ float tf32r(float x) {
    unsigned u;
    asm("cvt.rna.tf32.f32 %0, %1;" : "=r"(u) : "f"(x));
    return __uint_as_float(u);
}

__device__ __forceinline__ void mma_tf32(float d[4], const unsigned a[4], const unsigned b[2]) {
    asm volatile(
        "mma.sync.aligned.m16n8k8.row.col.f32.tf32.tf32.f32 "
        "{%0,%1,%2,%3},{%4,%5,%6,%7},{%8,%9},{%0,%1,%2,%3};\n"
        : "+f"(d[0]), "+f"(d[1]), "+f"(d[2]), "+f"(d[3])
        : "r"(a[0]), "r"(a[1]), "r"(a[2]), "r"(a[3]), "r"(b[0]), "r"(b[1]));
}

// ---------------- kernel 0: U/V precompute + agg zero ----------------
__global__ void prep_kernel(const float* __restrict__ x,
                            const float* __restrict__ We1,
                            const float* __restrict__ be1) {
    int row = blockIdx.x;          // b*512 + n
    int h = threadIdx.x;
    __shared__ float sx[DD];
    if (h < DD) sx[h] = x[row*DD + h];
    __syncthreads();
    float u = 0.f, v = be1[h];
#pragma unroll
    for (int d = 0; d < DD; d++) {
        u += sx[d] * We1[d*HH + h];
        v += sx[d] * We1[(DD+d)*HH + h];
    }
    g_U[row*HH + h] = u;
    g_V[row*HH + h] = v;
    g_agg[row*HH + h] = 0.f;
}

// ---------------- kernel 1: fused edge GEMM + adjacency reduction ----------------
// CTA: one (b, j, i-block of 128, h-half of 128).
// A[i,k] = relu(U[b,j,k] + V[b,i0+i,k]) generated into SMEM per 32-wide k chunk.
// E = A @ We2[:, h0:h0+128]; epilogue: agg[b,j,h0+c] += sum_i adj[b,i,j]*relu(E+be2).
#define LDA 36     // A smem row stride (floats): conflict-free fragment loads
#define LDW 136    // W smem row stride (floats): conflict-free fragment loads

__global__ __launch_bounds__(256, 2) void edge_kernel(
    const float* __restrict__ We2, const float* __restrict__ be2,
    const float* __restrict__ adj)
{
    const int b  = blockIdx.z;
    const int j  = blockIdx.y;
    const int ib = blockIdx.x >> 1;
    const int h0 = (blockIdx.x & 1) * 128;
    const int i0 = ib * 128;

    __shared__ __align__(16) float sA[128*LDA];
    __shared__ __align__(16) float sW[32*LDW];
    __shared__ __align__(16) float sU[HH];
    __shared__ float sAdj[128];
    __shared__ float sAgg[128];

    const int tid  = threadIdx.x;
    const int lane = tid & 31;
    const int wid  = tid >> 5;
    const int wm   = wid & 1;   // M-warp: rows wm*64 .. +64
    const int wn   = wid >> 1;  // N-warp: cols wn*32 .. +32

    const int rowj = b*NN + j;

    // prologue
    sU[tid] = g_U[rowj*HH + tid];
    if (tid < 128) {
        sAdj[tid] = adj[((size_t)(b*NN + i0 + tid))*NN + j];
        sAgg[tid] = 0.f;
    }

    float acc[4][4][4];
#pragma unroll
    for (int mt = 0; mt < 4; mt++)
#pragma unroll
        for (int nt = 0; nt < 4; nt++)
#pragma unroll
            for (int q = 0; q < 4; q++) acc[mt][nt][q] = 0.f;

    // A-gen assignment: thread -> (row ai, 16-wide k segment ak)
    const int ai = tid >> 1;
    const int ak = (tid & 1) * 16;
    const float* vbase = g_V + ((size_t)(b*NN + i0 + ai))*HH;

    // W-load assignment: thread -> (k row wk, 16-wide col segment wc)
    const int wk = tid >> 3;
    const int wc = (tid & 7) * 16;

    __syncthreads();

    for (int kc = 0; kc < HH; kc += 32) {
        // ---- stage A chunk: relu(U+V) -> tf32 ----
        {
            const float4* vp = (const float4*)(vbase + kc + ak);
            const float4* up = (const float4*)(sU + kc + ak);
            float* ap = sA + ai*LDA + ak;
#pragma unroll
            for (int q = 0; q < 4; q++) {
                float4 v = vp[q];
                float4 u = up[q];
                float4 a;
                a.x = tf32r(fmaxf(u.x + v.x, 0.f));
                a.y = tf32r(fmaxf(u.y + v.y, 0.f));
                a.z = tf32r(fmaxf(u.z + v.z, 0.f));
                a.w = tf32r(fmaxf(u.w + v.w, 0.f));
                *(float4*)(ap + q*4) = a;
            }
        }
        // ---- stage W chunk ----
        {
            const float4* wp = (const float4*)(We2 + (size_t)(kc + wk)*HH + h0 + wc);
            float* dp = sW + wk*LDW + wc;
#pragma unroll
            for (int q = 0; q < 4; q++) {
                float4 w = wp[q];
                w.x = tf32r(w.x); w.y = tf32r(w.y);
                w.z = tf32r(w.z); w.w = tf32r(w.w);
                *(float4*)(dp + q*4) = w;
            }
        }
        __syncthreads();

        const int r = lane >> 2;
        const int c = lane & 3;
#pragma unroll
        for (int ks = 0; ks < 4; ks++) {
            unsigned afr[4][4];
#pragma unroll
            for (int mt = 0; mt < 4; mt++) {
                const float* base = sA + (wm*64 + mt*16 + r)*LDA + ks*8 + c;
                afr[mt][0] = __float_as_uint(base[0]);
                afr[mt][1] = __float_as_uint(base[8*LDA]);
                afr[mt][2] = __float_as_uint(base[4]);
                afr[mt][3] = __float_as_uint(base[8*LDA + 4]);
            }
            unsigned bfr[4][2];
#pragma unroll
            for (int nt = 0; nt < 4; nt++) {
                const float* base = sW + (ks*8 + c)*LDW + wn*32 + nt*8 + r;
                bfr[nt][0] = __float_as_uint(base[0]);
                bfr[nt][1] = __float_as_uint(base[4*LDW]);
            }
#pragma unroll
            for (int mt = 0; mt < 4; mt++)
#pragma unroll
                for (int nt = 0; nt < 4; nt++)
                    mma_tf32(acc[mt][nt], afr[mt], bfr[nt]);
        }
        __syncthreads();
    }

    // ---- epilogue: agg[h] += sum_i adj[i] * relu(E[i,h] + be2[h]) ----
    {
        const int r  = lane >> 2;
        const int c2 = (lane & 3) * 2;
#pragma unroll
        for (int nt = 0; nt < 4; nt++) {
            const int col = wn*32 + nt*8 + c2;
            const float bb0 = __ldg(&be2[h0 + col]);
            const float bb1 = __ldg(&be2[h0 + col + 1]);
            float p0 = 0.f, p1 = 0.f;
#pragma unroll
            for (int mt = 0; mt < 4; mt++) {
                const int row = wm*64 + mt*16 + r;
                const float w0 = sAdj[row];
                const float w1 = sAdj[row + 8];
                p0 += w0 * fmaxf(acc[mt][nt][0] + bb0, 0.f)
                    + w1 * fmaxf(acc[mt][nt][2] + bb0, 0.f);
                p1 += w0 * fmaxf(acc[mt][nt][1] + bb1, 0.f)
                    + w1 * fmaxf(acc[mt][nt][3] + bb1, 0.f);
            }
#pragma unroll
            for (int off = 4; off < 32; off <<= 1) {
                p0 += __shfl_xor_sync(0xffffffffu, p0, off);
                p1 += __shfl_xor_sync(0xffffffffu, p1, off);
            }
            if (lane < 4) {
                atomicAdd(&sAgg[col], p0);
                atomicAdd(&sAgg[col + 1], p1);
            }
        }
    }
    __syncthreads();
    if (tid < 128) atomicAdd(&g_agg[rowj*HH + h0 + tid], sAgg[tid]);
}

// ---------------- kernel 2: tail MLP + log_softmax ----------------
// 16 (b,j) rows per CTA; each thread owns 2 output cols x 8 rows.
__global__ __launch_bounds__(256) void tail_kernel(
    const float* __restrict__ x,
    const float* __restrict__ Wn1, const float* __restrict__ bn1,
    const float* __restrict__ Wn2, const float* __restrict__ bn2,
    const float* __restrict__ Wo1, const float* __restrict__ bo1,
    const float* __restrict__ Wo,  const float* __restrict__ bo,
    float* __restrict__ out)
{
    const int row0 = blockIdx.x * 16;
    __shared__ float sA[16][HH];
    __shared__ float sB[16][HH];
    __shared__ float sx[16][DD];
    __shared__ float s5[16][DD];

    const int tid = threadIdx.x;
#pragma unroll
    for (int r = 0; r < 16; r++) sA[r][tid] = g_agg[(size_t)(row0 + r)*HH + tid];
    if (tid < 64) sx[tid >> 2][tid & 3] = x[(size_t)(row0 + (tid >> 2))*DD + (tid & 3)];
    __syncthreads();

    const int c0 = (tid & 127) * 2;
    const int rg = (tid >> 7) * 8;

    // layer 1: sA -> sB, relu
    {
        float a0[8], a1[8];
        const float bb0 = bn1[c0], bb1 = bn1[c0 + 1];
#pragma unroll
        for (int rr = 0; rr < 8; rr++) { a0[rr] = bb0; a1[rr] = bb1; }
        for (int k = 0; k < HH; k++) {
            float2 w = *(const float2*)&Wn1[(size_t)k*HH + c0];
#pragma unroll
            for (int rr = 0; rr < 8; rr++) {
                float v = sA[rg + rr][k];
                a0[rr] += v * w.x;
                a1[rr] += v * w.y;
            }
        }
#pragma unroll
        for (int rr = 0; rr < 8; rr++) {
            sB[rg + rr][c0]     = fmaxf(a0[rr], 0.f);
            sB[rg + rr][c0 + 1] = fmaxf(a1[rr], 0.f);
        }
    }
    __syncthreads();

    // layer 2: sB -> sA, relu
    {
        float a0[8], a1[8];
        const float bb0 = bn2[c0], bb1 = bn2[c0 + 1];
#pragma unroll
        for (int rr = 0; rr < 8; rr++) { a0[rr] = bb0; a1[rr] = bb1; }
        for (int k = 0; k < HH; k++) {
            float2 w = *(const float2*)&Wn2[(size_t)k*HH + c0];
#pragma unroll
            for (int rr = 0; rr < 8; rr++) {
                float v = sB[rg + rr][k];
                a0[rr] += v * w.x;
                a1[rr] += v * w.y;
            }
        }
#pragma unroll
        for (int rr = 0; rr < 8; rr++) {
            sA[rg + rr][c0]     = fmaxf(a0[rr], 0.f);
            sA[rg + rr][c0 + 1] = fmaxf(a1[rr], 0.f);
        }
    }
    __syncthreads();

    // layer 3: out4 = concat(x, out2) @ Wo1 + bo1  (NO relu): -> sB
    {
        float a0[8], a1[8];
        const float bb0 = bo1[c0], bb1 = bo1[c0 + 1];
#pragma unroll
        for (int rr = 0; rr < 8; rr++) { a0[rr] = bb0; a1[rr] = bb1; }
#pragma unroll
        for (int k = 0; k < DD; k++) {
            float2 w = *(const float2*)&Wo1[(size_t)k*HH + c0];
#pragma unroll
            for (int rr = 0; rr < 8; rr++) {
                float v = sx[rg + rr][k];
                a0[rr] += v * w.x;
                a1[rr] += v * w.y;
            }
        }
        for (int k = 0; k < HH; k++) {
            float2 w = *(const float2*)&Wo1[(size_t)(DD + k)*HH + c0];
#pragma unroll
            for (int rr = 0; rr < 8; rr++) {
                float v = sA[rg + rr][k];
                a0[rr] += v * w.x;
                a1[rr] += v * w.y;
            }
        }
#pragma unroll
        for (int rr = 0; rr < 8; rr++) {
            sB[rg + rr][c0]     = a0[rr];
            sB[rg + rr][c0 + 1] = a1[rr];
        }
    }
    __syncthreads();

    // layer 4: out5 = out4 @ Wo + bo, then log_softmax over D=4
    if (tid < 64) {
        const int r = tid >> 2, c = tid & 3;
        float acc = bo[c];
        for (int k = 0; k < HH; k++) acc += sB[r][k] * Wo[k*DD + c];
        s5[r][c] = acc;
    }
    __syncthreads();
    if (tid < 64) {
        const int r = tid >> 2, c = tid & 3;
        float v0 = s5[r][0], v1 = s5[r][1], v2 = s5[r][2], v3 = s5[r][3];
        float m = fmaxf(fmaxf(v0, v1), fmaxf(v2, v3));
        float lse = m + logf(expf(v0 - m) + expf(v1 - m) + expf(v2 - m) + expf(v3 - m));
        out[(size_t)(row0 + r)*DD + c] = s5[r][c] - lse;
    }
}

// ---------------- launch ----------------
extern "C" void kernel_launch(void* const* d_in, const int* in_sizes, int n_in,
                              void* d_out, int out_size) {
    const float* x   = (const float*)d_in[0];
    const float* adj = (const float*)d_in[1];
    const float* We1 = (const float*)d_in[2];
    const float* be1 = (const float*)d_in[3];
    const float* We2 = (const float*)d_in[4];
    const float* be2 = (const float*)d_in[5];
    const float* Wn1 = (const float*)d_in[6];
    const float* bn1 = (const float*)d_in[7];
    const float* Wn2 = (const float*)d_in[8];
    const float* bn2 = (const float*)d_in[9];
    const float* Wo1 = (const float*)d_in[10];
    const float* bo1 = (const float*)d_in[11];
    const float* Wo  = (const float*)d_in[12];
    const float* bo  = (const float*)d_in[13];
    float* out = (float*)d_out;

    prep_kernel<<<BB*NN, HH>>>(x, We1, be1);

    dim3 grid(8, NN, BB);   // 8 = 4 i-blocks x 2 h-halves
    edge_kernel<<<grid, 256>>>(We2, be2, adj);

    tail_kernel<<<(BB*NN)/16, 256>>>(x, Wn1, bn1, Wn2, bn2, Wo1, bo1, Wo, bo, out);
}

// round 16
// speedup vs baseline: 1.0003x; 1.0003x over previous
#include <cuda_runtime.h>
#include <cstdint>
#include <math.h>

#define BB 4
#define NN 512
#define DD 4
#define HH 256

// ---------------- device scratch (allocation-free) ----------------
__device__ float g_U[BB*NN*HH];    // x @ W_e1[:D]
__device__ float g_V[BB*NN*HH];    // x @ W_e1[D:] + b_e1
__device__ float g_agg[BB*NN*HH];  // adjacency-reduced edge features

// ---------------- helpers ----------------
__device__ __forceinline__ float tf32r(float x) {
    unsigned u;
    asm("cvt.rna.tf32.f32 %0, %1;" : "=r"(u) : "f"(x));
    return __uint_as_float(u);
}

__device__ __forceinline__ void mma_tf32(float d[4], const unsigned a[4], const unsigned b[2]) {
    asm volatile(
        "mma.sync.aligned.m16n8k8.row.col.f32.tf32.tf32.f32 "
        "{%0,%1,%2,%3},{%4,%5,%6,%7},{%8,%9},{%0,%1,%2,%3};\n"
        : "+f"(d[0]), "+f"(d[1]), "+f"(d[2]), "+f"(d[3])
        : "r"(a[0]), "r"(a[1]), "r"(a[2]), "r"(a[3]), "r"(b[0]), "r"(b[1]));
}

// ---------------- kernel 0: U/V precompute + agg zero ----------------
__global__ void prep_kernel(const float* __restrict__ x,
                            const float* __restrict__ We1,
                            const float* __restrict__ be1) {
    int row = blockIdx.x;          // b*512 + n
    int h = threadIdx.x;
    __shared__ float sx[DD];
    if (h < DD) sx[h] = x[row*DD + h];
    __syncthreads();
    float u = 0.f, v = be1[h];
#pragma unroll
    for (int d = 0; d < DD; d++) {
        u += sx[d] * We1[d*HH + h];
        v += sx[d] * We1[(DD+d)*HH + h];
    }
    g_U[row*HH + h] = u;
    g_V[row*HH + h] = v;
    g_agg[row*HH + h] = 0.f;
}

// ---------------- kernel 1: fused edge GEMM + adjacency reduction ----------------
// CTA: one (b, j, i-block of 128, h-half of 128).
// A[i,k] = relu(U[b,j,k] + V[b,i0+i,k]) generated into SMEM per 32-wide k chunk.
// E = A @ We2[:, h0:h0+128]; epilogue: agg[b,j,h0+c] += sum_i adj[b,i,j]*relu(E+be2).
#define LDA 36     // A smem row stride (floats): conflict-free fragment loads
#define LDW 136    // W smem row stride (floats): conflict-free fragment loads

__global__ __launch_bounds__(256, 2) void edge_kernel(
    const float* __restrict__ We2, const float* __restrict__ be2,
    const float* __restrict__ adj)
{
    const int b  = blockIdx.z;
    const int j  = blockIdx.y;
    const int ib = blockIdx.x >> 1;
    const int h0 = (blockIdx.x & 1) * 128;
    const int i0 = ib * 128;

    __shared__ __align__(16) float sA[128*LDA];
    __shared__ __align__(16) float sW[32*LDW];
    __shared__ __align__(16) float sU[HH];
    __shared__ float sAdj[128];
    __shared__ float sAgg[128];

    const int tid  = threadIdx.x;
    const int lane = tid & 31;
    const int wid  = tid >> 5;
    const int wm   = wid & 1;   // M-warp: rows wm*64 .. +64
    const int wn   = wid >> 1;  // N-warp: cols wn*32 .. +32

    const int rowj = b*NN + j;

    // prologue
    sU[tid] = g_U[rowj*HH + tid];
    if (tid < 128) {
        sAdj[tid] = adj[((size_t)(b*NN + i0 + tid))*NN + j];
        sAgg[tid] = 0.f;
    }

    float acc[4][4][4];
#pragma unroll
    for (int mt = 0; mt < 4; mt++)
#pragma unroll
        for (int nt = 0; nt < 4; nt++)
#pragma unroll
            for (int q = 0; q < 4; q++) acc[mt][nt][q] = 0.f;

    // A-gen assignment: thread -> (row ai, 16-wide k segment ak)
    const int ai = tid >> 1;
    const int ak = (tid & 1) * 16;
    const float* vbase = g_V + ((size_t)(b*NN + i0 + ai))*HH;

    // W-load assignment: thread -> (k row wk, 16-wide col segment wc)
    const int wk = tid >> 3;
    const int wc = (tid & 7) * 16;

    __syncthreads();

    for (int kc = 0; kc < HH; kc += 32) {
        // ---- stage A chunk: relu(U+V) -> tf32 ----
        {
            const float4* vp = (const float4*)(vbase + kc + ak);
            const float4* up = (const float4*)(sU + kc + ak);
            float* ap = sA + ai*LDA + ak;
#pragma unroll
            for (int q = 0; q < 4; q++) {
                float4 v = vp[q];
                float4 u = up[q];
                float4 a;
                a.x = tf32r(fmaxf(u.x + v.x, 0.f));
                a.y = tf32r(fmaxf(u.y + v.y, 0.f));
                a.z = tf32r(fmaxf(u.z + v.z, 0.f));
                a.w = tf32r(fmaxf(u.w + v.w, 0.f));
                *(float4*)(ap + q*4) = a;
            }
        }
        // ---- stage W chunk ----
        {
            const float4* wp = (const float4*)(We2 + (size_t)(kc + wk)*HH + h0 + wc);
            float* dp = sW + wk*LDW + wc;
#pragma unroll
            for (int q = 0; q < 4; q++) {
                float4 w = wp[q];
                w.x = tf32r(w.x); w.y = tf32r(w.y);
                w.z = tf32r(w.z); w.w = tf32r(w.w);
                *(float4*)(dp + q*4) = w;
            }
        }
        __syncthreads();

        const int r = lane >> 2;
        const int c = lane & 3;
#pragma unroll
        for (int ks = 0; ks < 4; ks++) {
            unsigned afr[4][4];
#pragma unroll
            for (int mt = 0; mt < 4; mt++) {
                const float* base = sA + (wm*64 + mt*16 + r)*LDA + ks*8 + c;
                afr[mt][0] = __float_as_uint(base[0]);
                afr[mt][1] = __float_as_uint(base[8*LDA]);
                afr[mt][2] = __float_as_uint(base[4]);
                afr[mt][3] = __float_as_uint(base[8*LDA + 4]);
            }
            unsigned bfr[4][2];
#pragma unroll
            for (int nt = 0; nt < 4; nt++) {
                const float* base = sW + (ks*8 + c)*LDW + wn*32 + nt*8 + r;
                bfr[nt][0] = __float_as_uint(base[0]);
                bfr[nt][1] = __float_as_uint(base[4*LDW]);
            }
#pragma unroll
            for (int mt = 0; mt < 4; mt++)
#pragma unroll
                for (int nt = 0; nt < 4; nt++)
                    mma_tf32(acc[mt][nt], afr[mt], bfr[nt]);
        }
        __syncthreads();
    }

    // ---- epilogue: agg[h] += sum_i adj[i] * relu(E[i,h] + be2[h]) ----
    {
        const int r  = lane >> 2;
        const int c2 = (lane & 3) * 2;
#pragma unroll
        for (int nt = 0; nt < 4; nt++) {
            const int col = wn*32 + nt*8 + c2;
            const float bb0 = __ldg(&be2[h0 + col]);
            const float bb1 = __ldg(&be2[h0 + col + 1]);
            float p0 = 0.f, p1 = 0.f;
#pragma unroll
            for (int mt = 0; mt < 4; mt++) {
                const int row = wm*64 + mt*16 + r;
                const float w0 = sAdj[row];
                const float w1 = sAdj[row + 8];
                p0 += w0 * fmaxf(acc[mt][nt][0] + bb0, 0.f)
                    + w1 * fmaxf(acc[mt][nt][2] + bb0, 0.f);
                p1 += w0 * fmaxf(acc[mt][nt][1] + bb1, 0.f)
                    + w1 * fmaxf(acc[mt][nt][3] + bb1, 0.f);
            }
#pragma unroll
            for (int off = 4; off < 32; off <<= 1) {
                p0 += __shfl_xor_sync(0xffffffffu, p0, off);
                p1 += __shfl_xor_sync(0xffffffffu, p1, off);
            }
            if (lane < 4) {
                atomicAdd(&sAgg[col], p0);
                atomicAdd(&sAgg[col + 1], p1);
            }
        }
    }
    __syncthreads();
    if (tid < 128) atomicAdd(&g_agg[rowj*HH + h0 + tid], sAgg[tid]);
}

// ---------------- kernel 2: tail MLP + log_softmax ----------------
// 16 (b,j) rows per CTA; each thread owns 2 output cols x 8 rows.
__global__ __launch_bounds__(256) void tail_kernel(
    const float* __restrict__ x,
    const float* __restrict__ Wn1, const float* __restrict__ bn1,
    const float* __restrict__ Wn2, const float* __restrict__ bn2,
    const float* __restrict__ Wo1, const float* __restrict__ bo1,
    const float* __restrict__ Wo,  const float* __restrict__ bo,
    float* __restrict__ out)
{
    const int row0 = blockIdx.x * 16;
    __shared__ float sA[16][HH];
    __shared__ float sB[16][HH];
    __shared__ float sx[16][DD];
    __shared__ float s5[16][DD];

    const int tid = threadIdx.x;
#pragma unroll
    for (int r = 0; r < 16; r++) sA[r][tid] = g_agg[(size_t)(row0 + r)*HH + tid];
    if (tid < 64) sx[tid >> 2][tid & 3] = x[(size_t)(row0 + (tid >> 2))*DD + (tid & 3)];
    __syncthreads();

    const int c0 = (tid & 127) * 2;
    const int rg = (tid >> 7) * 8;

    // layer 1: sA -> sB, relu
    {
        float a0[8], a1[8];
        const float bb0 = bn1[c0], bb1 = bn1[c0 + 1];
#pragma unroll
        for (int rr = 0; rr < 8; rr++) { a0[rr] = bb0; a1[rr] = bb1; }
        for (int k = 0; k < HH; k++) {
            float2 w = *(const float2*)&Wn1[(size_t)k*HH + c0];
#pragma unroll
            for (int rr = 0; rr < 8; rr++) {
                float v = sA[rg + rr][k];
                a0[rr] += v * w.x;
                a1[rr] += v * w.y;
            }
        }
#pragma unroll
        for (int rr = 0; rr < 8; rr++) {
            sB[rg + rr][c0]     = fmaxf(a0[rr], 0.f);
            sB[rg + rr][c0 + 1] = fmaxf(a1[rr], 0.f);
        }
    }
    __syncthreads();

    // layer 2: sB -> sA, relu
    {
        float a0[8], a1[8];
        const float bb0 = bn2[c0], bb1 = bn2[c0 + 1];
#pragma unroll
        for (int rr = 0; rr < 8; rr++) { a0[rr] = bb0; a1[rr] = bb1; }
        for (int k = 0; k < HH; k++) {
            float2 w = *(const float2*)&Wn2[(size_t)k*HH + c0];
#pragma unroll
            for (int rr = 0; rr < 8; rr++) {
                float v = sB[rg + rr][k];
                a0[rr] += v * w.x;
                a1[rr] += v * w.y;
            }
        }
#pragma unroll
        for (int rr = 0; rr < 8; rr++) {
            sA[rg + rr][c0]     = fmaxf(a0[rr], 0.f);
            sA[rg + rr][c0 + 1] = fmaxf(a1[rr], 0.f);
        }
    }
    __syncthreads();

    // layer 3: out4 = concat(x, out2) @ Wo1 + bo1  (NO relu): -> sB
    {
        float a0[8], a1[8];
        const float bb0 = bo1[c0], bb1 = bo1[c0 + 1];
#pragma unroll
        for (int rr = 0; rr < 8; rr++) { a0[rr] = bb0; a1[rr] = bb1; }
#pragma unroll
        for (int k = 0; k < DD; k++) {
            float2 w = *(const float2*)&Wo1[(size_t)k*HH + c0];
#pragma unroll
            for (int rr = 0; rr < 8; rr++) {
                float v = sx[rg + rr][k];
                a0[rr] += v * w.x;
                a1[rr] += v * w.y;
            }
        }
        for (int k = 0; k < HH; k++) {
            float2 w = *(const float2*)&Wo1[(size_t)(DD + k)*HH + c0];
#pragma unroll
            for (int rr = 0; rr < 8; rr++) {
                float v = sA[rg + rr][k];
                a0[rr] += v * w.x;
                a1[rr] += v * w.y;
            }
        }
#pragma unroll
        for (int rr = 0; rr < 8; rr++) {
            sB[rg + rr][c0]     = a0[rr];
            sB[rg + rr][c0 + 1] = a1[rr];
        }
    }
    __syncthreads();

    // layer 4: out5 = out4 @ Wo + bo, then log_softmax over D=4
    if (tid < 64) {
        const int r = tid >> 2, c = tid & 3;
        float acc = bo[c];
        for (int k = 0; k < HH; k++) acc += sB[r][k] * Wo[k*DD + c];
        s5[r][c] = acc;
    }
    __syncthreads();
    if (tid < 64) {
        const int r = tid >> 2, c = tid & 3;
        float v0 = s5[r][0], v1 = s5[r][1], v2 = s5[r][2], v3 = s5[r][3];
        float m = fmaxf(fmaxf(v0, v1), fmaxf(v2, v3));
        float lse = m + logf(expf(v0 - m) + expf(v1 - m) + expf(v2 - m) + expf(v3 - m));
        out[(size_t)(row0 + r)*DD + c] = s5[r][c] - lse;
    }
}

// ---------------- launch ----------------
extern "C" void kernel_launch(void* const* d_in, const int* in_sizes, int n_in,
                              void* d_out, int out_size) {
    const float* x   = (const float*)d_in[0];
    const float* adj = (const float*)d_in[1];
    const float* We1 = (const float*)d_in[2];
    const float* be1 = (const float*)d_in[3];
    const float* We2 = (const float*)d_in[4];
    const float* be2 = (const float*)d_in[5];
    const float* Wn1 = (const float*)d_in[6];
    const float* bn1 = (const float*)d_in[7];
    const float* Wn2 = (const float*)d_in[8];
    const float* bn2 = (const float*)d_in[9];
    const float* Wo1 = (const float*)d_in[10];
    const float* bo1 = (const float*)d_in[11];
    const float* Wo  = (const float*)d_in[12];
    const float* bo  = (const float*)d_in[13];
    float* out = (float*)d_out;

    prep_kernel<<<BB*NN, HH>>>(x, We1, be1);

    dim3 grid(8, NN, BB);   // 8 = 4 i-blocks x 2 h-halves
    edge_kernel<<<grid, 256>>>(We2, be2, adj);

    tail_kernel<<<(BB*NN)/16, 256>>>(x, Wn1, bn1, Wn2, bn2, Wo1, bo1, Wo, bo, out);
}